// round 7
// baseline (speedup 1.0000x reference)
#include <cuda_runtime.h>
#include <cuda_bf16.h>
#include <math.h>
#include <cstdint>

// ---------------------------------------------------------------------------
// Problem constants
// ---------------------------------------------------------------------------
#define DIM     256
#define KCODES  2048
#define NROWS   65536
#define BM      128            // z rows per CTA
#define BN      128            // codes per tile
#define NTILES  16             // KCODES / BN
#define NSTEPS  64             // 16 tiles * 4 chunks

#define MARGIN  1.0f           // >= 2.5x max plausible hh-score pair error

#define A_CHUNK_BYTES 16384    // 128 rows * 64 k * 2B
#define A_BYTES       65536    // 4 chunks (hh only)
#define B_CHUNK_BYTES 16384
#define QCAP    3584
// smem layout (bytes):
//   [0, 65536)         Ah (4 chunks)
//   [65536, 98304)     B double buffer
//   [98304, 98816)     rowminS[128] u32 (ordered-mapped float)
//   [98816, 99840)     rowbest[128] u64
//   [99840, 99872)     qcount (padded)
//   [99872, 114208)    queue[QCAP] u32
#define OFF_ROWMIN  98304
#define OFF_ROWBEST 98816
#define OFF_QCOUNT  99840
#define OFF_QUEUE   99872
#define SMEM_BYTES  114688

// ---------------------------------------------------------------------------
// Device scratch (static)
// ---------------------------------------------------------------------------
__device__ float g_enorm[KCODES];
__device__ int   g_index[NROWS];
__device__ float g_counts[KCODES];
__device__ float g_loss_sum;
__device__ __align__(16) __nv_bfloat16 g_es[KCODES * DIM];            // 1 MB (eh)
__device__ __align__(16) __nv_bfloat16 g_zs[(size_t)NROWS * DIM];     // 32 MB (zh)

// ---------------------------------------------------------------------------
// PTX helpers
// ---------------------------------------------------------------------------
__device__ __forceinline__ uint32_t smem_u32(const void* p) {
    uint32_t a;
    asm("{ .reg .u64 t; cvta.to.shared.u64 t, %1; cvt.u32.u64 %0, t; }"
        : "=r"(a) : "l"(p));
    return a;
}
__device__ __forceinline__ void cp16(uint32_t dst, const void* src) {
    asm volatile("cp.async.cg.shared.global [%0], [%1], 16;" :: "r"(dst), "l"(src));
}
#define CP_COMMIT() asm volatile("cp.async.commit_group;" ::: "memory")
#define CP_WAIT0()  asm volatile("cp.async.wait_group 0;" ::: "memory")

#define LDSM_X4(r, addr) \
    asm volatile("ldmatrix.sync.aligned.m8n8.x4.shared.b16 {%0,%1,%2,%3}, [%4];" \
        : "=r"((r)[0]), "=r"((r)[1]), "=r"((r)[2]), "=r"((r)[3]) : "r"(addr))

#define LDSM_X4B(r0, r1, r2, r3, addr) \
    asm volatile("ldmatrix.sync.aligned.m8n8.x4.shared.b16 {%0,%1,%2,%3}, [%4];" \
        : "=r"(r0), "=r"(r1), "=r"(r2), "=r"(r3) : "r"(addr))

#define MMA16816(d, a, b) \
    asm volatile("mma.sync.aligned.m16n8k16.row.col.f32.bf16.bf16.f32 " \
        "{%0,%1,%2,%3}, {%4,%5,%6,%7}, {%8,%9}, {%0,%1,%2,%3};" \
        : "+f"((d)[0]), "+f"((d)[1]), "+f"((d)[2]), "+f"((d)[3]) \
        : "r"((a)[0]), "r"((a)[1]), "r"((a)[2]), "r"((a)[3]), \
          "r"((b)[0]), "r"((b)[1]))

__device__ __forceinline__ uint32_t pack2h(float a, float b) {
    __nv_bfloat16 h0 = __float2bfloat16(a), h1 = __float2bfloat16(b);
    return ((uint32_t)__bfloat16_as_ushort(h1) << 16) |
           (uint32_t)__bfloat16_as_ushort(h0);
}

// Order-preserving float <-> uint maps (for atomicMin on shared u32).
__device__ __forceinline__ uint32_t fmap(float f) {
    uint32_t s = __float_as_uint(f);
    return (s & 0x80000000u) ? ~s : (s | 0x80000000u);
}
__device__ __forceinline__ float funmap(uint32_t u) {
    return (u & 0x80000000u) ? __uint_as_float(u & 0x7FFFFFFFu)
                             : __uint_as_float(~u);
}

// ---------------------------------------------------------------------------
// Prep 1: z -> g_zs (bf16 hi part). One thread per float4.
// ---------------------------------------------------------------------------
__global__ void prep_z_kernel(const float* __restrict__ z) {
    int i = blockIdx.x * blockDim.x + threadIdx.x;
    float4 v = ((const float4*)z)[i];
    ((uint2*)g_zs)[i] = make_uint2(pack2h(v.x, v.y), pack2h(v.z, v.w));
}

// ---------------------------------------------------------------------------
// Prep 2: e -> g_es (bf16 hi) + half-norms + zero scratch. One warp per code.
// ---------------------------------------------------------------------------
__global__ void prep_e_kernel(const float* __restrict__ e) {
    int t = blockIdx.x * blockDim.x + threadIdx.x;
    int w = t >> 5, l = t & 31;
    if (w < KCODES) {
        const float4* row = (const float4*)(e + (size_t)w * DIM);
        float4 a = row[2 * l], b = row[2 * l + 1];
        uint32_t ph[4] = {pack2h(a.x, a.y), pack2h(a.z, a.w),
                          pack2h(b.x, b.y), pack2h(b.z, b.w)};
        ((uint4*)g_es)[(size_t)w * 32 + l] = *(uint4*)ph;
        float s = a.x*a.x + a.y*a.y + a.z*a.z + a.w*a.w
                + b.x*b.x + b.y*b.y + b.z*b.z + b.w*b.w;
        #pragma unroll
        for (int o = 16; o; o >>= 1) s += __shfl_xor_sync(0xffffffffu, s, o);
        if (l == 0) { g_enorm[w] = 0.5f * s; g_counts[w] = 0.f; }
    }
    if (t == 0) g_loss_sum = 0.f;
}

// ---------------------------------------------------------------------------
// B tile fill: 128 codes x 64 k of eh into swizzled smem. step: tile*4+chunk.
// ---------------------------------------------------------------------------
__device__ __forceinline__ void fill_B(uint32_t sB, int step) {
    int tile = step >> 2, chunk = step & 3, buf = step & 1;
    const char* src0 = (const char*)g_es + (size_t)tile * BN * 512 + chunk * 128;
    uint32_t d0 = sB + buf * B_CHUNK_BYTES;
    #pragma unroll
    for (int o = 0; o < 8; ++o) {
        int idx = threadIdx.x + o * 128;
        int row = idx >> 3, seg = idx & 7;
        uint32_t dst = d0 + row * 128 + (((uint32_t)(seg ^ (row & 7))) << 4);
        cp16(dst, src0 + (size_t)row * 512 + seg * 16);
    }
}

// ---------------------------------------------------------------------------
// One hh chunk: 4 ks-steps of (8 LDSM.x4 + 32 MMA). Maps proven in R5/R6.
// ---------------------------------------------------------------------------
__device__ __forceinline__ void chunk_mma(
    uint32_t aBase, uint32_t bBase, int lane,
    float (&acc)[4][8][4], int wm, int wn)
{
    const int m = lane >> 3, r8 = lane & 7;
    #pragma unroll
    for (int ks = 0; ks < 4; ++ks) {
        uint32_t b[8][2];
        #pragma unroll
        for (int nb = 0; nb < 4; ++nb) {
            int code = wn + nb * 16 + ((m >> 1) << 3) + r8;
            int kseg = ks * 2 + (m & 1);
            uint32_t addr = bBase + code * 128 +
                            (((uint32_t)(kseg ^ (code & 7))) << 4);
            LDSM_X4B(b[2 * nb][0], b[2 * nb][1],
                     b[2 * nb + 1][0], b[2 * nb + 1][1], addr);
        }
        uint32_t a[4][4];
        #pragma unroll
        for (int mi = 0; mi < 4; ++mi) {
            int row = wm + mi * 16 + r8 + ((m & 1) << 3);
            int kseg = ks * 2 + (m >> 1);
            uint32_t addr = aBase + row * 128 +
                            (((uint32_t)(kseg ^ (row & 7))) << 4);
            LDSM_X4(a[mi], addr);
        }
        #pragma unroll
        for (int mi = 0; mi < 4; ++mi)
            #pragma unroll
            for (int ni = 0; ni < 8; ++ni)
                MMA16816(acc[mi][ni], a[mi], b[ni]);
    }
}

// ---------------------------------------------------------------------------
// Exact fp32 rescore of (row, code); atomicMin packed (score|code) key.
// ---------------------------------------------------------------------------
__device__ __forceinline__ void exact_rescore(
    const float* __restrict__ z, const float* __restrict__ e,
    int row0, int rloc, int code, unsigned long long* rowbest)
{
    const float4* zr = (const float4*)(z + (size_t)(row0 + rloc) * DIM);
    const float4* er = (const float4*)(e + (size_t)code * DIM);
    float a0 = 0.f, a1 = 0.f, a2 = 0.f, a3 = 0.f;
    #pragma unroll 8
    for (int i = 0; i < 64; ++i) {
        float4 zv = __ldg(&zr[i]);
        float4 ev = __ldg(&er[i]);
        a0 += zv.x * ev.x; a1 += zv.y * ev.y;
        a2 += zv.z * ev.z; a3 += zv.w * ev.w;
    }
    float sc = __ldg(&g_enorm[code]) - ((a0 + a1) + (a2 + a3));
    unsigned long long key = ((unsigned long long)fmap(sc) << 32) | (uint32_t)code;
    atomicMin(&rowbest[rloc], key);
}

// ---------------------------------------------------------------------------
// Main kernel: single-pass hh GEMM + online candidate collection +
// margin-gated exact fp32 rescore.
// ---------------------------------------------------------------------------
__global__ void __launch_bounds__(128, 2)
argmin_mma_kernel(const float* __restrict__ z, const float* __restrict__ e,
                  float* __restrict__ out_idx) {
    extern __shared__ char smem[];
    const int tid = threadIdx.x, lane = tid & 31, w = tid >> 5;
    const int row0 = blockIdx.x * BM;
    const int wm = (w >> 1) * 64, wn = (w & 1) * 64;
    const uint32_t sA = smem_u32(smem);
    const uint32_t sB = sA + A_BYTES;
    uint32_t* rowminS = (uint32_t*)(smem + OFF_ROWMIN);
    unsigned long long* rowbest = (unsigned long long*)(smem + OFF_ROWBEST);
    int* qcount = (int*)(smem + OFF_QCOUNT);
    uint32_t* queue = (uint32_t*)(smem + OFF_QUEUE);

    rowbest[tid] = ~0ull;
    rowminS[tid] = fmap(3.0e38f);     // +huge, well-defined unmap
    if (tid == 0) *qcount = 0;

    // ---- Prologue: Ah (4 chunks) + B step 0 ----
    {
        const char* gA = (const char*)g_zs + (size_t)row0 * 512;
        for (int o = tid; o < 4096; o += 128) {
            int chunk = o >> 10, rem = o & 1023;
            int row = rem >> 3, seg = rem & 7;
            uint32_t dst = sA + chunk * A_CHUNK_BYTES + row * 128 +
                           (((uint32_t)(seg ^ (row & 7))) << 4);
            cp16(dst, gA + (size_t)row * 512 + chunk * 128 + seg * 16);
        }
        fill_B(sB, 0);
        CP_COMMIT();
    }
    __syncthreads();   // rowminS/rowbest/qcount init visible

    // ================= Single GEMM pass with online gating ================
    int s = 0;
    for (int tile = 0; tile < NTILES; ++tile) {
        float acc[4][8][4];
        #pragma unroll
        for (int mi = 0; mi < 4; ++mi)
            #pragma unroll
            for (int ni = 0; ni < 8; ++ni)
                #pragma unroll
                for (int r = 0; r < 4; ++r) acc[mi][ni][r] = 0.f;
        for (int chunk = 0; chunk < 4; ++chunk, ++s) {
            CP_WAIT0();
            __syncthreads();
            if (s + 1 < NSTEPS) { fill_B(sB, s + 1); CP_COMMIT(); }
            chunk_mma(sA + chunk * A_CHUNK_BYTES,
                      sB + (s & 1) * B_CHUNK_BYTES, lane, acc, wm, wn);
        }

        // ---- Epilogue: gate candidates against shared running row min ----
        float en0[8], en1[8];
        #pragma unroll
        for (int ni = 0; ni < 8; ++ni) {
            int c0 = tile * BN + wn + ni * 8 + ((lane & 3) << 1);
            en0[ni] = __ldg(&g_enorm[c0]);
            en1[ni] = __ldg(&g_enorm[c0 + 1]);
        }
        #pragma unroll
        for (int mi = 0; mi < 4; ++mi) {
            #pragma unroll
            for (int h = 0; h < 2; ++h) {
                int rloc = wm + mi * 16 + (lane >> 2) + h * 8;
                float cur = funmap(rowminS[rloc]) + MARGIN;
                float vmin = 3.0e38f;
                #pragma unroll
                for (int ni = 0; ni < 8; ++ni) {
                    int c0 = tile * BN + wn + ni * 8 + ((lane & 3) << 1);
                    float v0 = en0[ni] - acc[mi][ni][2 * h];
                    float v1 = en1[ni] - acc[mi][ni][2 * h + 1];
                    if (v0 < cur) {
                        int qi = atomicAdd(qcount, 1);
                        if (qi < QCAP) queue[qi] = ((uint32_t)rloc << 11) | (uint32_t)c0;
                        else exact_rescore(z, e, row0, rloc, c0, rowbest);
                    }
                    cur = fminf(cur, v0 + MARGIN);
                    vmin = fminf(vmin, v0);
                    if (v1 < cur) {
                        int qi = atomicAdd(qcount, 1);
                        if (qi < QCAP) queue[qi] = ((uint32_t)rloc << 11) | (uint32_t)(c0 + 1);
                        else exact_rescore(z, e, row0, rloc, c0 + 1, rowbest);
                    }
                    cur = fminf(cur, v1 + MARGIN);
                    vmin = fminf(vmin, v1);
                }
                atomicMin(&rowminS[rloc], fmap(vmin));
            }
        }
    }

    // ======================= Exact fp32 rescore ============================
    __syncthreads();
    int qn = *qcount; if (qn > QCAP) qn = QCAP;
    for (int q = tid; q < qn; q += 128) {
        uint32_t ent = queue[q];
        exact_rescore(z, e, row0, (int)(ent >> 11), (int)(ent & 2047u), rowbest);
    }
    __syncthreads();

    // ---- Outputs: each thread owns one row ----
    {
        int bi = (int)(rowbest[tid] & 0xFFFFFFFFull);
        int row = row0 + tid;
        g_index[row] = bi;
        out_idx[row] = (float)bi;
        atomicAdd(&g_counts[bi], 1.0f);
    }
}

// ---------------------------------------------------------------------------
// Gather z_q + commitment-loss partials.
// ---------------------------------------------------------------------------
__global__ void gather_loss_kernel(const float* __restrict__ z,
                                   const float* __restrict__ e,
                                   float* __restrict__ out) {
    int i = blockIdx.x * blockDim.x + threadIdx.x;
    int row = i >> 6;
    int c4 = i & 63;
    int idx = g_index[row];
    float4 ev = ((const float4*)e)[(size_t)idx * 64 + c4];
    float4 zv = ((const float4*)z)[i];
    ((float4*)out)[i] = ev;
    float dx = ev.x - zv.x, dy = ev.y - zv.y;
    float dz = ev.z - zv.z, dw = ev.w - zv.w;
    float ls = dx * dx + dy * dy + dz * dz + dw * dw;

    __shared__ float red[32];
    #pragma unroll
    for (int o = 16; o; o >>= 1) ls += __shfl_xor_sync(0xffffffffu, ls, o);
    int l = threadIdx.x & 31, wq = threadIdx.x >> 5;
    if (l == 0) red[wq] = ls;
    __syncthreads();
    if (wq == 0) {
        float v = (l < ((int)blockDim.x >> 5)) ? red[l] : 0.f;
        #pragma unroll
        for (int o = 16; o; o >>= 1) v += __shfl_xor_sync(0xffffffffu, v, o);
        if (l == 0) atomicAdd(&g_loss_sum, v);
    }
}

// ---------------------------------------------------------------------------
// Finalize: loss scalar + perplexity.
// ---------------------------------------------------------------------------
__global__ void finalize_kernel(float* __restrict__ out) {
    const float invN = 1.0f / (float)NROWS;
    float s = 0.f;
    for (int k = threadIdx.x; k < KCODES; k += blockDim.x) {
        float p = g_counts[k] * invN;
        s += p * logf(p + 1e-10f);
    }
    __shared__ float red[32];
    #pragma unroll
    for (int o = 16; o; o >>= 1) s += __shfl_xor_sync(0xffffffffu, s, o);
    int l = threadIdx.x & 31, wq = threadIdx.x >> 5;
    if (l == 0) red[wq] = s;
    __syncthreads();
    if (wq == 0) {
        float v = (l < ((int)blockDim.x >> 5)) ? red[l] : 0.f;
        #pragma unroll
        for (int o = 16; o; o >>= 1) v += __shfl_xor_sync(0xffffffffu, v, o);
        if (l == 0) {
            const size_t NZ = (size_t)NROWS * DIM;
            out[NZ] = 0.25f * g_loss_sum / (float)NZ;
            out[NZ + 1 + NROWS] = expf(-v);
        }
    }
}

// ---------------------------------------------------------------------------
// Output layout (flattened tuple, float32):
//   [0, N*D) z_q_st | [N*D] loss | [N*D+1, +N) indices | [N*D+1+N] perplexity
// ---------------------------------------------------------------------------
extern "C" void kernel_launch(void* const* d_in, const int* in_sizes, int n_in,
                              void* d_out, int out_size) {
    const float* z = (const float*)d_in[0];
    const float* e = (const float*)d_in[1];
    float* out = (float*)d_out;

    cudaFuncSetAttribute(argmin_mma_kernel,
                         cudaFuncAttributeMaxDynamicSharedMemorySize, SMEM_BYTES);

    prep_z_kernel<<<(NROWS * 64) / 256, 256>>>(z);
    prep_e_kernel<<<KCODES * 32 / 256, 256>>>(e);
    argmin_mma_kernel<<<NROWS / BM, 128, SMEM_BYTES>>>(
        z, e, out + (size_t)NROWS * DIM + 1);
    gather_loss_kernel<<<(NROWS * (DIM / 4)) / 256, 256>>>(z, e, out);
    finalize_kernel<<<1, 256>>>(out);
}

// round 8
// speedup vs baseline: 4.5551x; 4.5551x over previous
#include <cuda_runtime.h>
#include <cuda_bf16.h>
#include <math.h>
#include <cstdint>

// ---------------------------------------------------------------------------
// Problem constants
// ---------------------------------------------------------------------------
#define DIM     256
#define KCODES  2048
#define NROWS   65536
#define BM      128            // z rows per CTA
#define BN      128            // codes per tile
#define NTILES  16             // KCODES / BN
#define NSTEPS  64             // 16 tiles * 4 chunks

#define MARGIN  1.5f           // >= 2x max plausible hh-score error (~0.7)
#define QSLAB   4096           // global queue entries per CTA

#define A_CHUNK_BYTES 16384    // 128 rows * 64 k * 2B
#define A_BYTES       65536    // 4 chunks (hh only)
#define B_CHUNK_BYTES 16384
// smem layout (bytes):
//   [0, 65536)         Ah (4 chunks)
//   [65536, 98304)     B double buffer
//   [98304, 98816)     rowminS[128] u32 (order-mapped float)
//   [98816, 99840)     rowbest[128] u64
//   [99840, 99872)     qcount (padded)
#define OFF_ROWMIN  98304
#define OFF_ROWBEST 98816
#define OFF_QCOUNT  99840
#define SMEM_BYTES  100352

// ---------------------------------------------------------------------------
// Device scratch (static)
// ---------------------------------------------------------------------------
__device__ float g_enorm[KCODES];
__device__ int   g_index[NROWS];
__device__ float g_counts[KCODES];
__device__ float g_loss_sum;
__device__ __align__(16) __nv_bfloat16 g_es[KCODES * DIM];            // 1 MB (eh)
__device__ __align__(16) __nv_bfloat16 g_zs[(size_t)NROWS * DIM];     // 32 MB (zh)
__device__ uint32_t g_queue[(NROWS / BM) * QSLAB];                    // 8 MB

// ---------------------------------------------------------------------------
// PTX helpers
// ---------------------------------------------------------------------------
__device__ __forceinline__ uint32_t smem_u32(const void* p) {
    uint32_t a;
    asm("{ .reg .u64 t; cvta.to.shared.u64 t, %1; cvt.u32.u64 %0, t; }"
        : "=r"(a) : "l"(p));
    return a;
}
__device__ __forceinline__ void cp16(uint32_t dst, const void* src) {
    asm volatile("cp.async.cg.shared.global [%0], [%1], 16;" :: "r"(dst), "l"(src));
}
#define CP_COMMIT() asm volatile("cp.async.commit_group;" ::: "memory")
#define CP_WAIT0()  asm volatile("cp.async.wait_group 0;" ::: "memory")

#define LDSM_X4(r, addr) \
    asm volatile("ldmatrix.sync.aligned.m8n8.x4.shared.b16 {%0,%1,%2,%3}, [%4];" \
        : "=r"((r)[0]), "=r"((r)[1]), "=r"((r)[2]), "=r"((r)[3]) : "r"(addr))

#define LDSM_X4B(r0, r1, r2, r3, addr) \
    asm volatile("ldmatrix.sync.aligned.m8n8.x4.shared.b16 {%0,%1,%2,%3}, [%4];" \
        : "=r"(r0), "=r"(r1), "=r"(r2), "=r"(r3) : "r"(addr))

#define MMA16816(d, a, b) \
    asm volatile("mma.sync.aligned.m16n8k16.row.col.f32.bf16.bf16.f32 " \
        "{%0,%1,%2,%3}, {%4,%5,%6,%7}, {%8,%9}, {%0,%1,%2,%3};" \
        : "+f"((d)[0]), "+f"((d)[1]), "+f"((d)[2]), "+f"((d)[3]) \
        : "r"((a)[0]), "r"((a)[1]), "r"((a)[2]), "r"((a)[3]), \
          "r"((b)[0]), "r"((b)[1]))

__device__ __forceinline__ uint32_t pack2h(float a, float b) {
    __nv_bfloat16 h0 = __float2bfloat16(a), h1 = __float2bfloat16(b);
    return ((uint32_t)__bfloat16_as_ushort(h1) << 16) |
           (uint32_t)__bfloat16_as_ushort(h0);
}

// Order-preserving float <-> uint maps (atomicMin on u32).
__device__ __forceinline__ uint32_t fmap(float f) {
    uint32_t s = __float_as_uint(f);
    return (s & 0x80000000u) ? ~s : (s | 0x80000000u);
}
__device__ __forceinline__ float funmap(uint32_t u) {
    return (u & 0x80000000u) ? __uint_as_float(u & 0x7FFFFFFFu)
                             : __uint_as_float(~u);
}

// ---------------------------------------------------------------------------
// Prep 1: z -> g_zs (bf16 hi). One thread per float4.
// ---------------------------------------------------------------------------
__global__ void prep_z_kernel(const float* __restrict__ z) {
    int i = blockIdx.x * blockDim.x + threadIdx.x;
    float4 v = ((const float4*)z)[i];
    ((uint2*)g_zs)[i] = make_uint2(pack2h(v.x, v.y), pack2h(v.z, v.w));
}

// ---------------------------------------------------------------------------
// Prep 2: e -> g_es (bf16 hi) + half-norms + zero scratch. One warp per code.
// ---------------------------------------------------------------------------
__global__ void prep_e_kernel(const float* __restrict__ e) {
    int t = blockIdx.x * blockDim.x + threadIdx.x;
    int w = t >> 5, l = t & 31;
    if (w < KCODES) {
        const float4* row = (const float4*)(e + (size_t)w * DIM);
        float4 a = row[2 * l], b = row[2 * l + 1];
        uint32_t ph[4] = {pack2h(a.x, a.y), pack2h(a.z, a.w),
                          pack2h(b.x, b.y), pack2h(b.z, b.w)};
        ((uint4*)g_es)[(size_t)w * 32 + l] = *(uint4*)ph;
        float s = a.x*a.x + a.y*a.y + a.z*a.z + a.w*a.w
                + b.x*b.x + b.y*b.y + b.z*b.z + b.w*b.w;
        #pragma unroll
        for (int o = 16; o; o >>= 1) s += __shfl_xor_sync(0xffffffffu, s, o);
        if (l == 0) { g_enorm[w] = 0.5f * s; g_counts[w] = 0.f; }
    }
    if (t == 0) g_loss_sum = 0.f;
}

// ---------------------------------------------------------------------------
// B tile fill: 128 codes x 64 k of eh into swizzled smem. step: tile*4+chunk.
// ---------------------------------------------------------------------------
__device__ __forceinline__ void fill_B(uint32_t sB, int step) {
    int tile = step >> 2, chunk = step & 3, buf = step & 1;
    const char* src0 = (const char*)g_es + (size_t)tile * BN * 512 + chunk * 128;
    uint32_t d0 = sB + buf * B_CHUNK_BYTES;
    #pragma unroll
    for (int o = 0; o < 8; ++o) {
        int idx = threadIdx.x + o * 128;
        int row = idx >> 3, seg = idx & 7;
        uint32_t dst = d0 + row * 128 + (((uint32_t)(seg ^ (row & 7))) << 4);
        cp16(dst, src0 + (size_t)row * 512 + seg * 16);
    }
}

// ---------------------------------------------------------------------------
// One hh chunk: 4 ks-steps of (8 LDSM.x4 + 32 MMA). Maps proven R5/R6.
// ---------------------------------------------------------------------------
__device__ __forceinline__ void chunk_mma(
    uint32_t aBase, uint32_t bBase, int lane,
    float (&acc)[4][8][4], int wm, int wn)
{
    const int m = lane >> 3, r8 = lane & 7;
    #pragma unroll
    for (int ks = 0; ks < 4; ++ks) {
        uint32_t b[8][2];
        #pragma unroll
        for (int nb = 0; nb < 4; ++nb) {
            int code = wn + nb * 16 + ((m >> 1) << 3) + r8;
            int kseg = ks * 2 + (m & 1);
            uint32_t addr = bBase + code * 128 +
                            (((uint32_t)(kseg ^ (code & 7))) << 4);
            LDSM_X4B(b[2 * nb][0], b[2 * nb][1],
                     b[2 * nb + 1][0], b[2 * nb + 1][1], addr);
        }
        uint32_t a[4][4];
        #pragma unroll
        for (int mi = 0; mi < 4; ++mi) {
            int row = wm + mi * 16 + r8 + ((m & 1) << 3);
            int kseg = ks * 2 + (m >> 1);
            uint32_t addr = aBase + row * 128 +
                            (((uint32_t)(kseg ^ (row & 7))) << 4);
            LDSM_X4(a[mi], addr);
        }
        #pragma unroll
        for (int mi = 0; mi < 4; ++mi)
            #pragma unroll
            for (int ni = 0; ni < 8; ++ni)
                MMA16816(acc[mi][ni], a[mi], b[ni]);
    }
}

// ---------------------------------------------------------------------------
// Exact fp32 rescore; atomicMin packed (score|code) key. Cold path noinline.
// ---------------------------------------------------------------------------
__device__ __noinline__ void exact_rescore(
    const float* __restrict__ z, const float* __restrict__ e,
    int row0, int rloc, int code, unsigned long long* rowbest)
{
    const float4* zr = (const float4*)(z + (size_t)(row0 + rloc) * DIM);
    const float4* er = (const float4*)(e + (size_t)code * DIM);
    float a0 = 0.f, a1 = 0.f, a2 = 0.f, a3 = 0.f;
    #pragma unroll 8
    for (int i = 0; i < 64; ++i) {
        float4 zv = __ldg(&zr[i]);
        float4 ev = __ldg(&er[i]);
        a0 += zv.x * ev.x; a1 += zv.y * ev.y;
        a2 += zv.z * ev.z; a3 += zv.w * ev.w;
    }
    float sc = __ldg(&g_enorm[code]) - ((a0 + a1) + (a2 + a3));
    unsigned long long key = ((unsigned long long)fmap(sc) << 32) | (uint32_t)code;
    atomicMin(&rowbest[rloc], key);
}

// ---------------------------------------------------------------------------
// Main kernel: single-pass hh GEMM; per-tile two-phase epilogue
// (register min -> shared rowmin; then constant-threshold gating to a global
// per-CTA queue); exact fp32 rescore of the queue at the end.
// ---------------------------------------------------------------------------
__global__ void __launch_bounds__(128, 2)
argmin_mma_kernel(const float* __restrict__ z, const float* __restrict__ e,
                  float* __restrict__ out_idx) {
    extern __shared__ char smem[];
    const int tid = threadIdx.x, lane = tid & 31, w = tid >> 5;
    const int row0 = blockIdx.x * BM;
    const int wm = (w >> 1) * 64, wn = (w & 1) * 64;
    const uint32_t sA = smem_u32(smem);
    const uint32_t sB = sA + A_BYTES;
    uint32_t* rowminS = (uint32_t*)(smem + OFF_ROWMIN);
    unsigned long long* rowbest = (unsigned long long*)(smem + OFF_ROWBEST);
    int* qcount = (int*)(smem + OFF_QCOUNT);
    uint32_t* myq = g_queue + (size_t)blockIdx.x * QSLAB;

    rowbest[tid] = ~0ull;
    rowminS[tid] = fmap(3.0e38f);
    if (tid == 0) *qcount = 0;

    // ---- Prologue: Ah (4 chunks) + B step 0 ----
    {
        const char* gA = (const char*)g_zs + (size_t)row0 * 512;
        for (int o = tid; o < 4096; o += 128) {
            int chunk = o >> 10, rem = o & 1023;
            int row = rem >> 3, seg = rem & 7;
            uint32_t dst = sA + chunk * A_CHUNK_BYTES + row * 128 +
                           (((uint32_t)(seg ^ (row & 7))) << 4);
            cp16(dst, gA + (size_t)row * 512 + chunk * 128 + seg * 16);
        }
        fill_B(sB, 0);
        CP_COMMIT();
    }
    __syncthreads();   // shared init visible

    // ===================== Single GEMM pass with gating ====================
    int s = 0;
    for (int tile = 0; tile < NTILES; ++tile) {
        float acc[4][8][4];
        #pragma unroll
        for (int mi = 0; mi < 4; ++mi)
            #pragma unroll
            for (int ni = 0; ni < 8; ++ni)
                #pragma unroll
                for (int r = 0; r < 4; ++r) acc[mi][ni][r] = 0.f;
        for (int chunk = 0; chunk < 4; ++chunk, ++s) {
            CP_WAIT0();
            __syncthreads();
            if (s + 1 < NSTEPS) { fill_B(sB, s + 1); CP_COMMIT(); }
            chunk_mma(sA + chunk * A_CHUNK_BYTES,
                      sB + (s & 1) * B_CHUNK_BYTES, lane, acc, wm, wn);
        }

        // ---- Phase 1: scores in place, register min, shared atomicMin ----
        #pragma unroll
        for (int ni = 0; ni < 8; ++ni) {
            int c0 = tile * BN + wn + ni * 8 + ((lane & 3) << 1);
            float e0 = __ldg(&g_enorm[c0]);
            float e1 = __ldg(&g_enorm[c0 + 1]);
            #pragma unroll
            for (int mi = 0; mi < 4; ++mi) {
                acc[mi][ni][0] = e0 - acc[mi][ni][0];
                acc[mi][ni][1] = e1 - acc[mi][ni][1];
                acc[mi][ni][2] = e0 - acc[mi][ni][2];
                acc[mi][ni][3] = e1 - acc[mi][ni][3];
            }
        }
        #pragma unroll
        for (int mi = 0; mi < 4; ++mi) {
            #pragma unroll
            for (int h = 0; h < 2; ++h) {
                float vmin = fminf(acc[mi][0][2*h], acc[mi][0][2*h+1]);
                #pragma unroll
                for (int ni = 1; ni < 8; ++ni)
                    vmin = fminf(vmin, fminf(acc[mi][ni][2*h], acc[mi][ni][2*h+1]));
                int rloc = wm + mi * 16 + (lane >> 2) + h * 8;
                atomicMin(&rowminS[rloc], fmap(vmin));
            }
        }
        __syncthreads();

        // ---- Phase 2: constant-threshold gating into global queue ----
        #pragma unroll
        for (int mi = 0; mi < 4; ++mi) {
            #pragma unroll
            for (int h = 0; h < 2; ++h) {
                int rloc = wm + mi * 16 + (lane >> 2) + h * 8;
                float thr = funmap(rowminS[rloc]) + MARGIN;
                #pragma unroll
                for (int ni = 0; ni < 8; ++ni) {
                    int c0 = tile * BN + wn + ni * 8 + ((lane & 3) << 1);
                    if (acc[mi][ni][2*h] < thr) {
                        int qi = atomicAdd(qcount, 1);
                        if (qi < QSLAB) myq[qi] = ((uint32_t)rloc << 11) | (uint32_t)c0;
                        else exact_rescore(z, e, row0, rloc, c0, rowbest);
                    }
                    if (acc[mi][ni][2*h+1] < thr) {
                        int qi = atomicAdd(qcount, 1);
                        if (qi < QSLAB) myq[qi] = ((uint32_t)rloc << 11) | (uint32_t)(c0 + 1);
                        else exact_rescore(z, e, row0, rloc, c0 + 1, rowbest);
                    }
                }
            }
        }
    }

    // ======================= Exact fp32 rescore ============================
    __syncthreads();
    int qn = *qcount; if (qn > QSLAB) qn = QSLAB;
    for (int q = tid; q < qn; q += 128) {
        uint32_t ent = myq[q];
        exact_rescore(z, e, row0, (int)(ent >> 11), (int)(ent & 2047u), rowbest);
    }
    __syncthreads();

    // ---- Outputs: each thread owns one row ----
    {
        int bi = (int)(rowbest[tid] & 0xFFFFFFFFull);
        int row = row0 + tid;
        g_index[row] = bi;
        out_idx[row] = (float)bi;
        atomicAdd(&g_counts[bi], 1.0f);
    }
}

// ---------------------------------------------------------------------------
// Gather z_q + commitment-loss partials.
// ---------------------------------------------------------------------------
__global__ void gather_loss_kernel(const float* __restrict__ z,
                                   const float* __restrict__ e,
                                   float* __restrict__ out) {
    int i = blockIdx.x * blockDim.x + threadIdx.x;
    int row = i >> 6;
    int c4 = i & 63;
    int idx = g_index[row];
    float4 ev = ((const float4*)e)[(size_t)idx * 64 + c4];
    float4 zv = ((const float4*)z)[i];
    ((float4*)out)[i] = ev;
    float dx = ev.x - zv.x, dy = ev.y - zv.y;
    float dz = ev.z - zv.z, dw = ev.w - zv.w;
    float ls = dx * dx + dy * dy + dz * dz + dw * dw;

    __shared__ float red[32];
    #pragma unroll
    for (int o = 16; o; o >>= 1) ls += __shfl_xor_sync(0xffffffffu, ls, o);
    int l = threadIdx.x & 31, wq = threadIdx.x >> 5;
    if (l == 0) red[wq] = ls;
    __syncthreads();
    if (wq == 0) {
        float v = (l < ((int)blockDim.x >> 5)) ? red[l] : 0.f;
        #pragma unroll
        for (int o = 16; o; o >>= 1) v += __shfl_xor_sync(0xffffffffu, v, o);
        if (l == 0) atomicAdd(&g_loss_sum, v);
    }
}

// ---------------------------------------------------------------------------
// Finalize: loss scalar + perplexity.
// ---------------------------------------------------------------------------
__global__ void finalize_kernel(float* __restrict__ out) {
    const float invN = 1.0f / (float)NROWS;
    float s = 0.f;
    for (int k = threadIdx.x; k < KCODES; k += blockDim.x) {
        float p = g_counts[k] * invN;
        s += p * logf(p + 1e-10f);
    }
    __shared__ float red[32];
    #pragma unroll
    for (int o = 16; o; o >>= 1) s += __shfl_xor_sync(0xffffffffu, s, o);
    int l = threadIdx.x & 31, wq = threadIdx.x >> 5;
    if (l == 0) red[wq] = s;
    __syncthreads();
    if (wq == 0) {
        float v = (l < ((int)blockDim.x >> 5)) ? red[l] : 0.f;
        #pragma unroll
        for (int o = 16; o; o >>= 1) v += __shfl_xor_sync(0xffffffffu, v, o);
        if (l == 0) {
            const size_t NZ = (size_t)NROWS * DIM;
            out[NZ] = 0.25f * g_loss_sum / (float)NZ;
            out[NZ + 1 + NROWS] = expf(-v);
        }
    }
}

// ---------------------------------------------------------------------------
// Output layout (flattened tuple, float32):
//   [0, N*D) z_q_st | [N*D] loss | [N*D+1, +N) indices | [N*D+1+N] perplexity
// ---------------------------------------------------------------------------
extern "C" void kernel_launch(void* const* d_in, const int* in_sizes, int n_in,
                              void* d_out, int out_size) {
    const float* z = (const float*)d_in[0];
    const float* e = (const float*)d_in[1];
    float* out = (float*)d_out;

    cudaFuncSetAttribute(argmin_mma_kernel,
                         cudaFuncAttributeMaxDynamicSharedMemorySize, SMEM_BYTES);

    prep_z_kernel<<<(NROWS * 64) / 256, 256>>>(z);
    prep_e_kernel<<<KCODES * 32 / 256, 256>>>(e);
    argmin_mma_kernel<<<NROWS / BM, 128, SMEM_BYTES>>>(
        z, e, out + (size_t)NROWS * DIM + 1);
    gather_loss_kernel<<<(NROWS * (DIM / 4)) / 256, 256>>>(z, e, out);
    finalize_kernel<<<1, 256>>>(out);
}

// round 9
// speedup vs baseline: 5.2009x; 1.1418x over previous
#include <cuda_runtime.h>
#include <cuda_bf16.h>
#include <math.h>
#include <cstdint>

// ---------------------------------------------------------------------------
// Problem constants
// ---------------------------------------------------------------------------
#define DIM     256
#define KCODES  2048
#define NROWS   65536
#define BM      128            // z rows per CTA
#define BN      128            // codes per tile
#define NTILES  16             // KCODES / BN
#define NSTEPS  64             // 16 tiles * 4 chunks

#define MARGIN  1.5f           // >= 2x max plausible hh-score error (~0.7)
#define QSLAB   8192           // global queue entries per CTA (exp ~500)

#define A_CHUNK_BYTES 16384    // 128 rows * 64 k * 2B
#define A_BYTES       65536    // 4 chunks (hh only)
#define B_CHUNK_BYTES 16384
// smem layout (bytes):
//   [0, 65536)         Ah (4 chunks)
//   [65536, 98304)     B double buffer
//   [98304, 98816)     rowminS[128] u32 (order-mapped float)
//   [98816, 99840)     rowbest[128] u64
//   [99840, 99844)     qcount
//   [99844, 99848)     qovf
#define OFF_ROWMIN  98304
#define OFF_ROWBEST 98816
#define OFF_QCOUNT  99840
#define OFF_QOVF    99844
#define SMEM_BYTES  100352

// ---------------------------------------------------------------------------
// Device scratch (static)
// ---------------------------------------------------------------------------
__device__ float g_enorm[KCODES];
__device__ int   g_index[NROWS];
__device__ float g_counts[KCODES];
__device__ float g_loss_sum;
__device__ __align__(16) __nv_bfloat16 g_es[KCODES * DIM];            // 1 MB (eh)
__device__ __align__(16) __nv_bfloat16 g_zs[(size_t)NROWS * DIM];     // 32 MB (zh)
__device__ uint32_t g_queue[(NROWS / BM) * QSLAB];                    // 16 MB

// ---------------------------------------------------------------------------
// PTX helpers
// ---------------------------------------------------------------------------
__device__ __forceinline__ uint32_t smem_u32(const void* p) {
    uint32_t a;
    asm("{ .reg .u64 t; cvta.to.shared.u64 t, %1; cvt.u32.u64 %0, t; }"
        : "=r"(a) : "l"(p));
    return a;
}
__device__ __forceinline__ void cp16(uint32_t dst, const void* src) {
    asm volatile("cp.async.cg.shared.global [%0], [%1], 16;" :: "r"(dst), "l"(src));
}
#define CP_COMMIT() asm volatile("cp.async.commit_group;" ::: "memory")
#define CP_WAIT0()  asm volatile("cp.async.wait_group 0;" ::: "memory")

#define LDSM_X4(r, addr) \
    asm volatile("ldmatrix.sync.aligned.m8n8.x4.shared.b16 {%0,%1,%2,%3}, [%4];" \
        : "=r"((r)[0]), "=r"((r)[1]), "=r"((r)[2]), "=r"((r)[3]) : "r"(addr))

#define LDSM_X4B(r0, r1, r2, r3, addr) \
    asm volatile("ldmatrix.sync.aligned.m8n8.x4.shared.b16 {%0,%1,%2,%3}, [%4];" \
        : "=r"(r0), "=r"(r1), "=r"(r2), "=r"(r3) : "r"(addr))

#define MMA16816(d, a, b) \
    asm volatile("mma.sync.aligned.m16n8k16.row.col.f32.bf16.bf16.f32 " \
        "{%0,%1,%2,%3}, {%4,%5,%6,%7}, {%8,%9}, {%0,%1,%2,%3};" \
        : "+f"((d)[0]), "+f"((d)[1]), "+f"((d)[2]), "+f"((d)[3]) \
        : "r"((a)[0]), "r"((a)[1]), "r"((a)[2]), "r"((a)[3]), \
          "r"((b)[0]), "r"((b)[1]))

__device__ __forceinline__ uint32_t pack2h(float a, float b) {
    __nv_bfloat16 h0 = __float2bfloat16(a), h1 = __float2bfloat16(b);
    return ((uint32_t)__bfloat16_as_ushort(h1) << 16) |
           (uint32_t)__bfloat16_as_ushort(h0);
}

// Order-preserving float <-> uint maps (atomicMin on u32).
__device__ __forceinline__ uint32_t fmap(float f) {
    uint32_t s = __float_as_uint(f);
    return (s & 0x80000000u) ? ~s : (s | 0x80000000u);
}
__device__ __forceinline__ float funmap(uint32_t u) {
    return (u & 0x80000000u) ? __uint_as_float(u & 0x7FFFFFFFu)
                             : __uint_as_float(~u);
}

// ---------------------------------------------------------------------------
// Prep 1: z -> g_zs (bf16 hi). One thread per float4.
// ---------------------------------------------------------------------------
__global__ void prep_z_kernel(const float* __restrict__ z) {
    int i = blockIdx.x * blockDim.x + threadIdx.x;
    float4 v = ((const float4*)z)[i];
    ((uint2*)g_zs)[i] = make_uint2(pack2h(v.x, v.y), pack2h(v.z, v.w));
}

// ---------------------------------------------------------------------------
// Prep 2: e -> g_es (bf16 hi) + half-norms + zero scratch. One warp per code.
// ---------------------------------------------------------------------------
__global__ void prep_e_kernel(const float* __restrict__ e) {
    int t = blockIdx.x * blockDim.x + threadIdx.x;
    int w = t >> 5, l = t & 31;
    if (w < KCODES) {
        const float4* row = (const float4*)(e + (size_t)w * DIM);
        float4 a = row[2 * l], b = row[2 * l + 1];
        uint32_t ph[4] = {pack2h(a.x, a.y), pack2h(a.z, a.w),
                          pack2h(b.x, b.y), pack2h(b.z, b.w)};
        ((uint4*)g_es)[(size_t)w * 32 + l] = *(uint4*)ph;
        float s = a.x*a.x + a.y*a.y + a.z*a.z + a.w*a.w
                + b.x*b.x + b.y*b.y + b.z*b.z + b.w*b.w;
        #pragma unroll
        for (int o = 16; o; o >>= 1) s += __shfl_xor_sync(0xffffffffu, s, o);
        if (l == 0) { g_enorm[w] = 0.5f * s; g_counts[w] = 0.f; }
    }
    if (t == 0) g_loss_sum = 0.f;
}

// ---------------------------------------------------------------------------
// B tile fill: 128 codes x 64 k of eh into swizzled smem. step: tile*4+chunk.
// ---------------------------------------------------------------------------
__device__ __forceinline__ void fill_B(uint32_t sB, int step) {
    int tile = step >> 2, chunk = step & 3, buf = step & 1;
    const char* src0 = (const char*)g_es + (size_t)tile * BN * 512 + chunk * 128;
    uint32_t d0 = sB + buf * B_CHUNK_BYTES;
    #pragma unroll
    for (int o = 0; o < 8; ++o) {
        int idx = threadIdx.x + o * 128;
        int row = idx >> 3, seg = idx & 7;
        uint32_t dst = d0 + row * 128 + (((uint32_t)(seg ^ (row & 7))) << 4);
        cp16(dst, src0 + (size_t)row * 512 + seg * 16);
    }
}

// ---------------------------------------------------------------------------
// One hh chunk: 4 ks-steps of (8 LDSM.x4 + 32 MMA). Maps proven R5/R6.
// ---------------------------------------------------------------------------
__device__ __forceinline__ void chunk_mma(
    uint32_t aBase, uint32_t bBase, int lane,
    float (&acc)[4][8][4], int wm, int wn)
{
    const int m = lane >> 3, r8 = lane & 7;
    #pragma unroll
    for (int ks = 0; ks < 4; ++ks) {
        uint32_t b[8][2];
        #pragma unroll
        for (int nb = 0; nb < 4; ++nb) {
            int code = wn + nb * 16 + ((m >> 1) << 3) + r8;
            int kseg = ks * 2 + (m & 1);
            uint32_t addr = bBase + code * 128 +
                            (((uint32_t)(kseg ^ (code & 7))) << 4);
            LDSM_X4B(b[2 * nb][0], b[2 * nb][1],
                     b[2 * nb + 1][0], b[2 * nb + 1][1], addr);
        }
        uint32_t a[4][4];
        #pragma unroll
        for (int mi = 0; mi < 4; ++mi) {
            int row = wm + mi * 16 + r8 + ((m & 1) << 3);
            int kseg = ks * 2 + (m >> 1);
            uint32_t addr = aBase + row * 128 +
                            (((uint32_t)(kseg ^ (row & 7))) << 4);
            LDSM_X4(a[mi], addr);
        }
        #pragma unroll
        for (int mi = 0; mi < 4; ++mi)
            #pragma unroll
            for (int ni = 0; ni < 8; ++ni)
                MMA16816(acc[mi][ni], a[mi], b[ni]);
    }
}

// ---------------------------------------------------------------------------
// Exact fp32 rescore; atomicMin packed (score|code) key.
// Only called AFTER the GEMM loop (acc dead) -> safe to inline.
// ---------------------------------------------------------------------------
__device__ __forceinline__ void exact_rescore(
    const float* __restrict__ z, const float* __restrict__ e,
    int row0, int rloc, int code, unsigned long long* rowbest)
{
    const float4* zr = (const float4*)(z + (size_t)(row0 + rloc) * DIM);
    const float4* er = (const float4*)(e + (size_t)code * DIM);
    float a0 = 0.f, a1 = 0.f, a2 = 0.f, a3 = 0.f;
    #pragma unroll 8
    for (int i = 0; i < 64; ++i) {
        float4 zv = __ldg(&zr[i]);
        float4 ev = __ldg(&er[i]);
        a0 += zv.x * ev.x; a1 += zv.y * ev.y;
        a2 += zv.z * ev.z; a3 += zv.w * ev.w;
    }
    float sc = __ldg(&g_enorm[code]) - ((a0 + a1) + (a2 + a3));
    unsigned long long key = ((unsigned long long)fmap(sc) << 32) | (uint32_t)code;
    atomicMin(&rowbest[rloc], key);
}

// ---------------------------------------------------------------------------
// Main kernel: single-pass hh GEMM; per-tile two-phase epilogue with NO
// function calls (overflow -> sticky flag); post-loop exact rescore; cold
// brute-force fallback if the queue ever overflowed.
// ---------------------------------------------------------------------------
__global__ void __launch_bounds__(128, 2)
argmin_mma_kernel(const float* __restrict__ z, const float* __restrict__ e,
                  float* __restrict__ out_idx) {
    extern __shared__ char smem[];
    const int tid = threadIdx.x, lane = tid & 31, w = tid >> 5;
    const int row0 = blockIdx.x * BM;
    const int wm = (w >> 1) * 64, wn = (w & 1) * 64;
    const uint32_t sA = smem_u32(smem);
    const uint32_t sB = sA + A_BYTES;
    uint32_t* rowminS = (uint32_t*)(smem + OFF_ROWMIN);
    unsigned long long* rowbest = (unsigned long long*)(smem + OFF_ROWBEST);
    int* qcount = (int*)(smem + OFF_QCOUNT);
    int* qovf   = (int*)(smem + OFF_QOVF);
    uint32_t* myq = g_queue + (size_t)blockIdx.x * QSLAB;

    rowbest[tid] = ~0ull;
    rowminS[tid] = fmap(3.0e38f);
    if (tid == 0) { *qcount = 0; *qovf = 0; }

    // ---- Prologue: Ah (4 chunks) + B step 0 ----
    {
        const char* gA = (const char*)g_zs + (size_t)row0 * 512;
        for (int o = tid; o < 4096; o += 128) {
            int chunk = o >> 10, rem = o & 1023;
            int row = rem >> 3, seg = rem & 7;
            uint32_t dst = sA + chunk * A_CHUNK_BYTES + row * 128 +
                           (((uint32_t)(seg ^ (row & 7))) << 4);
            cp16(dst, gA + (size_t)row * 512 + chunk * 128 + seg * 16);
        }
        fill_B(sB, 0);
        CP_COMMIT();
    }
    __syncthreads();   // shared init visible

    // ===================== Single GEMM pass with gating ====================
    int s = 0;
    for (int tile = 0; tile < NTILES; ++tile) {
        float acc[4][8][4];
        #pragma unroll
        for (int mi = 0; mi < 4; ++mi)
            #pragma unroll
            for (int ni = 0; ni < 8; ++ni)
                #pragma unroll
                for (int r = 0; r < 4; ++r) acc[mi][ni][r] = 0.f;
        for (int chunk = 0; chunk < 4; ++chunk, ++s) {
            CP_WAIT0();
            __syncthreads();
            if (s + 1 < NSTEPS) { fill_B(sB, s + 1); CP_COMMIT(); }
            chunk_mma(sA + chunk * A_CHUNK_BYTES,
                      sB + (s & 1) * B_CHUNK_BYTES, lane, acc, wm, wn);
        }

        // ---- Phase 1: scores in place, register min, shared atomicMin ----
        #pragma unroll
        for (int ni = 0; ni < 8; ++ni) {
            int c0 = tile * BN + wn + ni * 8 + ((lane & 3) << 1);
            float e0 = __ldg(&g_enorm[c0]);
            float e1 = __ldg(&g_enorm[c0 + 1]);
            #pragma unroll
            for (int mi = 0; mi < 4; ++mi) {
                acc[mi][ni][0] = e0 - acc[mi][ni][0];
                acc[mi][ni][1] = e1 - acc[mi][ni][1];
                acc[mi][ni][2] = e0 - acc[mi][ni][2];
                acc[mi][ni][3] = e1 - acc[mi][ni][3];
            }
        }
        #pragma unroll
        for (int mi = 0; mi < 4; ++mi) {
            #pragma unroll
            for (int h = 0; h < 2; ++h) {
                float vmin = fminf(acc[mi][0][2*h], acc[mi][0][2*h+1]);
                #pragma unroll
                for (int ni = 1; ni < 8; ++ni)
                    vmin = fminf(vmin, fminf(acc[mi][ni][2*h], acc[mi][ni][2*h+1]));
                int rloc = wm + mi * 16 + (lane >> 2) + h * 8;
                atomicMin(&rowminS[rloc], fmap(vmin));
            }
        }
        __syncthreads();

        // ---- Phase 2: constant-threshold gating; NO calls, flag overflow ----
        #pragma unroll
        for (int mi = 0; mi < 4; ++mi) {
            #pragma unroll
            for (int h = 0; h < 2; ++h) {
                int rloc = wm + mi * 16 + (lane >> 2) + h * 8;
                float thr = funmap(rowminS[rloc]) + MARGIN;
                #pragma unroll
                for (int ni = 0; ni < 8; ++ni) {
                    int c0 = tile * BN + wn + ni * 8 + ((lane & 3) << 1);
                    if (acc[mi][ni][2*h] < thr) {
                        int qi = atomicAdd(qcount, 1);
                        if (qi < QSLAB) myq[qi] = ((uint32_t)rloc << 11) | (uint32_t)c0;
                        else *qovf = 1;
                    }
                    if (acc[mi][ni][2*h+1] < thr) {
                        int qi = atomicAdd(qcount, 1);
                        if (qi < QSLAB) myq[qi] = ((uint32_t)rloc << 11) | (uint32_t)(c0 + 1);
                        else *qovf = 1;
                    }
                }
            }
        }
    }

    // ======================= Exact fp32 rescore ============================
    __syncthreads();
    int qn = *qcount; if (qn > QSLAB) qn = QSLAB;
    for (int q = tid; q < qn; q += 128) {
        uint32_t ent = myq[q];
        exact_rescore(z, e, row0, (int)(ent >> 11), (int)(ent & 2047u), rowbest);
    }
    // Cold fallback: queue overflowed (never in practice) -> brute force.
    if (*qovf) {
        for (int code = 0; code < KCODES; ++code)
            exact_rescore(z, e, row0, tid, code, rowbest);
    }
    __syncthreads();

    // ---- Outputs: each thread owns one row ----
    {
        int bi = (int)(rowbest[tid] & 0xFFFFFFFFull);
        int row = row0 + tid;
        g_index[row] = bi;
        out_idx[row] = (float)bi;
        atomicAdd(&g_counts[bi], 1.0f);
    }
}

// ---------------------------------------------------------------------------
// Gather z_q + commitment-loss partials.
// ---------------------------------------------------------------------------
__global__ void gather_loss_kernel(const float* __restrict__ z,
                                   const float* __restrict__ e,
                                   float* __restrict__ out) {
    int i = blockIdx.x * blockDim.x + threadIdx.x;
    int row = i >> 6;
    int c4 = i & 63;
    int idx = g_index[row];
    float4 ev = ((const float4*)e)[(size_t)idx * 64 + c4];
    float4 zv = ((const float4*)z)[i];
    ((float4*)out)[i] = ev;
    float dx = ev.x - zv.x, dy = ev.y - zv.y;
    float dz = ev.z - zv.z, dw = ev.w - zv.w;
    float ls = dx * dx + dy * dy + dz * dz + dw * dw;

    __shared__ float red[32];
    #pragma unroll
    for (int o = 16; o; o >>= 1) ls += __shfl_xor_sync(0xffffffffu, ls, o);
    int l = threadIdx.x & 31, wq = threadIdx.x >> 5;
    if (l == 0) red[wq] = ls;
    __syncthreads();
    if (wq == 0) {
        float v = (l < ((int)blockDim.x >> 5)) ? red[l] : 0.f;
        #pragma unroll
        for (int o = 16; o; o >>= 1) v += __shfl_xor_sync(0xffffffffu, v, o);
        if (l == 0) atomicAdd(&g_loss_sum, v);
    }
}

// ---------------------------------------------------------------------------
// Finalize: loss scalar + perplexity.
// ---------------------------------------------------------------------------
__global__ void finalize_kernel(float* __restrict__ out) {
    const float invN = 1.0f / (float)NROWS;
    float s = 0.f;
    for (int k = threadIdx.x; k < KCODES; k += blockDim.x) {
        float p = g_counts[k] * invN;
        s += p * logf(p + 1e-10f);
    }
    __shared__ float red[32];
    #pragma unroll
    for (int o = 16; o; o >>= 1) s += __shfl_xor_sync(0xffffffffu, s, o);
    int l = threadIdx.x & 31, wq = threadIdx.x >> 5;
    if (l == 0) red[wq] = s;
    __syncthreads();
    if (wq == 0) {
        float v = (l < ((int)blockDim.x >> 5)) ? red[l] : 0.f;
        #pragma unroll
        for (int o = 16; o; o >>= 1) v += __shfl_xor_sync(0xffffffffu, v, o);
        if (l == 0) {
            const size_t NZ = (size_t)NROWS * DIM;
            out[NZ] = 0.25f * g_loss_sum / (float)NZ;
            out[NZ + 1 + NROWS] = expf(-v);
        }
    }
}

// ---------------------------------------------------------------------------
// Output layout (flattened tuple, float32):
//   [0, N*D) z_q_st | [N*D] loss | [N*D+1, +N) indices | [N*D+1+N] perplexity
// ---------------------------------------------------------------------------
extern "C" void kernel_launch(void* const* d_in, const int* in_sizes, int n_in,
                              void* d_out, int out_size) {
    const float* z = (const float*)d_in[0];
    const float* e = (const float*)d_in[1];
    float* out = (float*)d_out;

    cudaFuncSetAttribute(argmin_mma_kernel,
                         cudaFuncAttributeMaxDynamicSharedMemorySize, SMEM_BYTES);

    prep_z_kernel<<<(NROWS * 64) / 256, 256>>>(z);
    prep_e_kernel<<<KCODES * 32 / 256, 256>>>(e);
    argmin_mma_kernel<<<NROWS / BM, 128, SMEM_BYTES>>>(
        z, e, out + (size_t)NROWS * DIM + 1);
    gather_loss_kernel<<<(NROWS * (DIM / 4)) / 256, 256>>>(z, e, out);
    finalize_kernel<<<1, 256>>>(out);
}

// round 10
// speedup vs baseline: 6.4107x; 1.2326x over previous
#include <cuda_runtime.h>
#include <cuda_bf16.h>
#include <math.h>
#include <cstdint>

// ---------------------------------------------------------------------------
// Problem constants
// ---------------------------------------------------------------------------
#define DIM     256
#define KCODES  2048
#define NROWS   65536
#define BM      128            // z rows per CTA
#define BN      128            // codes per tile
#define NTILES  16             // KCODES / BN
#define NSTEPS  64             // 16 tiles * 4 chunks

#define MARGIN  1.5f           // > 2x max plausible hh-score error (~0.7)
#define QSLAB   8192           // global queue entries per CTA (exp ~500)

#define A_CHUNK_BYTES 16384    // 128 rows * 64 k * 2B
#define A_BYTES       65536    // 4 chunks (hh only)
#define B_CHUNK_BYTES 16384
// smem layout (bytes):
//   [0, 65536)         Ah (4 chunks)
//   [65536, 98304)     B double buffer
//   [98304, 98816)     rowminS[128] u32 (order-mapped float)
//   [98816, 99840)     rowbest[128] u64
//   [99840, 99844)     qcount
//   [99844, 99848)     qovf
#define OFF_ROWMIN  98304
#define OFF_ROWBEST 98816
#define OFF_QCOUNT  99840
#define OFF_QOVF    99844
#define SMEM_BYTES  100352

// ---------------------------------------------------------------------------
// Device scratch (static)
// ---------------------------------------------------------------------------
__device__ float g_enorm[KCODES];
__device__ int   g_index[NROWS];
__device__ float g_counts[KCODES];
__device__ float g_loss_sum;
__device__ __align__(16) __nv_bfloat16 g_es[KCODES * DIM];            // 1 MB (eh)
__device__ __align__(16) __nv_bfloat16 g_zs[(size_t)NROWS * DIM];     // 32 MB (zh)
__device__ uint32_t g_queue[(NROWS / BM) * QSLAB];                    // 16 MB

// ---------------------------------------------------------------------------
// PTX helpers
// ---------------------------------------------------------------------------
__device__ __forceinline__ uint32_t smem_u32(const void* p) {
    uint32_t a;
    asm("{ .reg .u64 t; cvta.to.shared.u64 t, %1; cvt.u32.u64 %0, t; }"
        : "=r"(a) : "l"(p));
    return a;
}
__device__ __forceinline__ void cp16(uint32_t dst, const void* src) {
    asm volatile("cp.async.cg.shared.global [%0], [%1], 16;" :: "r"(dst), "l"(src));
}
#define CP_COMMIT() asm volatile("cp.async.commit_group;" ::: "memory")
#define CP_WAIT0()  asm volatile("cp.async.wait_group 0;" ::: "memory")

#define LDSM_X4(r, addr) \
    asm volatile("ldmatrix.sync.aligned.m8n8.x4.shared.b16 {%0,%1,%2,%3}, [%4];" \
        : "=r"((r)[0]), "=r"((r)[1]), "=r"((r)[2]), "=r"((r)[3]) : "r"(addr))

#define LDSM_X4B(r0, r1, r2, r3, addr) \
    asm volatile("ldmatrix.sync.aligned.m8n8.x4.shared.b16 {%0,%1,%2,%3}, [%4];" \
        : "=r"(r0), "=r"(r1), "=r"(r2), "=r"(r3) : "r"(addr))

#define MMA16816(d, a, b) \
    asm volatile("mma.sync.aligned.m16n8k16.row.col.f32.bf16.bf16.f32 " \
        "{%0,%1,%2,%3}, {%4,%5,%6,%7}, {%8,%9}, {%0,%1,%2,%3};" \
        : "+f"((d)[0]), "+f"((d)[1]), "+f"((d)[2]), "+f"((d)[3]) \
        : "r"((a)[0]), "r"((a)[1]), "r"((a)[2]), "r"((a)[3]), \
          "r"((b)[0]), "r"((b)[1]))

__device__ __forceinline__ uint32_t pack2h(float a, float b) {
    __nv_bfloat16 h0 = __float2bfloat16(a), h1 = __float2bfloat16(b);
    return ((uint32_t)__bfloat16_as_ushort(h1) << 16) |
           (uint32_t)__bfloat16_as_ushort(h0);
}

// Order-preserving float <-> uint maps (atomicMin on u32).
__device__ __forceinline__ uint32_t fmap(float f) {
    uint32_t s = __float_as_uint(f);
    return (s & 0x80000000u) ? ~s : (s | 0x80000000u);
}
__device__ __forceinline__ float funmap(uint32_t u) {
    return (u & 0x80000000u) ? __uint_as_float(u & 0x7FFFFFFFu)
                             : __uint_as_float(~u);
}

// ---------------------------------------------------------------------------
// Prep 1: z -> g_zs (bf16 hi). One thread per float4.
// ---------------------------------------------------------------------------
__global__ void prep_z_kernel(const float* __restrict__ z) {
    int i = blockIdx.x * blockDim.x + threadIdx.x;
    float4 v = ((const float4*)z)[i];
    ((uint2*)g_zs)[i] = make_uint2(pack2h(v.x, v.y), pack2h(v.z, v.w));
}

// ---------------------------------------------------------------------------
// Prep 2: e -> g_es (bf16 hi) + half-norms + zero scratch. One warp per code.
// ---------------------------------------------------------------------------
__global__ void prep_e_kernel(const float* __restrict__ e) {
    int t = blockIdx.x * blockDim.x + threadIdx.x;
    int w = t >> 5, l = t & 31;
    if (w < KCODES) {
        const float4* row = (const float4*)(e + (size_t)w * DIM);
        float4 a = row[2 * l], b = row[2 * l + 1];
        uint32_t ph[4] = {pack2h(a.x, a.y), pack2h(a.z, a.w),
                          pack2h(b.x, b.y), pack2h(b.z, b.w)};
        ((uint4*)g_es)[(size_t)w * 32 + l] = *(uint4*)ph;
        float s = a.x*a.x + a.y*a.y + a.z*a.z + a.w*a.w
                + b.x*b.x + b.y*b.y + b.z*b.z + b.w*b.w;
        #pragma unroll
        for (int o = 16; o; o >>= 1) s += __shfl_xor_sync(0xffffffffu, s, o);
        if (l == 0) { g_enorm[w] = 0.5f * s; g_counts[w] = 0.f; }
    }
    if (t == 0) g_loss_sum = 0.f;
}

// ---------------------------------------------------------------------------
// B tile fill: 128 codes x 64 k of eh into swizzled smem. step: tile*4+chunk.
// ---------------------------------------------------------------------------
__device__ __forceinline__ void fill_B(uint32_t sB, int step) {
    int tile = step >> 2, chunk = step & 3, buf = step & 1;
    const char* src0 = (const char*)g_es + (size_t)tile * BN * 512 + chunk * 128;
    uint32_t d0 = sB + buf * B_CHUNK_BYTES;
    #pragma unroll
    for (int o = 0; o < 8; ++o) {
        int idx = threadIdx.x + o * 128;
        int row = idx >> 3, seg = idx & 7;
        uint32_t dst = d0 + row * 128 + (((uint32_t)(seg ^ (row & 7))) << 4);
        cp16(dst, src0 + (size_t)row * 512 + seg * 16);
    }
}

// ---------------------------------------------------------------------------
// One hh chunk: 4 ks-steps of (8 LDSM.x4 + 32 MMA). Maps proven R5/R6.
// ---------------------------------------------------------------------------
__device__ __forceinline__ void chunk_mma(
    uint32_t aBase, uint32_t bBase, int lane,
    float (&acc)[4][8][4], int wm, int wn)
{
    const int m = lane >> 3, r8 = lane & 7;
    #pragma unroll
    for (int ks = 0; ks < 4; ++ks) {
        uint32_t b[8][2];
        #pragma unroll
        for (int nb = 0; nb < 4; ++nb) {
            int code = wn + nb * 16 + ((m >> 1) << 3) + r8;
            int kseg = ks * 2 + (m & 1);
            uint32_t addr = bBase + code * 128 +
                            (((uint32_t)(kseg ^ (code & 7))) << 4);
            LDSM_X4B(b[2 * nb][0], b[2 * nb][1],
                     b[2 * nb + 1][0], b[2 * nb + 1][1], addr);
        }
        uint32_t a[4][4];
        #pragma unroll
        for (int mi = 0; mi < 4; ++mi) {
            int row = wm + mi * 16 + r8 + ((m & 1) << 3);
            int kseg = ks * 2 + (m >> 1);
            uint32_t addr = aBase + row * 128 +
                            (((uint32_t)(kseg ^ (row & 7))) << 4);
            LDSM_X4(a[mi], addr);
        }
        #pragma unroll
        for (int mi = 0; mi < 4; ++mi)
            #pragma unroll
            for (int ni = 0; ni < 8; ++ni)
                MMA16816(acc[mi][ni], a[mi], b[ni]);
    }
}

// ---------------------------------------------------------------------------
// Exact fp32 rescore; atomicMin packed (score|code) key.
// Only called AFTER the GEMM loop (acc dead).
// ---------------------------------------------------------------------------
__device__ __forceinline__ void exact_rescore(
    const float* __restrict__ z, const float* __restrict__ e,
    int row0, int rloc, int code, unsigned long long* rowbest)
{
    const float4* zr = (const float4*)(z + (size_t)(row0 + rloc) * DIM);
    const float4* er = (const float4*)(e + (size_t)code * DIM);
    float a0 = 0.f, a1 = 0.f, a2 = 0.f, a3 = 0.f;
    #pragma unroll 8
    for (int i = 0; i < 64; ++i) {
        float4 zv = __ldg(&zr[i]);
        float4 ev = __ldg(&er[i]);
        a0 += zv.x * ev.x; a1 += zv.y * ev.y;
        a2 += zv.z * ev.z; a3 += zv.w * ev.w;
    }
    float sc = __ldg(&g_enorm[code]) - ((a0 + a1) + (a2 + a3));
    unsigned long long key = ((unsigned long long)fmap(sc) << 32) | (uint32_t)code;
    atomicMin(&rowbest[rloc], key);
}

// ---------------------------------------------------------------------------
// Main kernel: single-pass hh GEMM; branch-free hit-mask gating (one cold
// branch per (mi,h) slice per tile); post-loop exact rescore; cold
// brute-force fallback if queue overflowed.
// ---------------------------------------------------------------------------
__global__ void __launch_bounds__(128, 2)
argmin_mma_kernel(const float* __restrict__ z, const float* __restrict__ e,
                  float* __restrict__ out_idx) {
    extern __shared__ char smem[];
    const int tid = threadIdx.x, lane = tid & 31, w = tid >> 5;
    const int row0 = blockIdx.x * BM;
    const int wm = (w >> 1) * 64, wn = (w & 1) * 64;
    const uint32_t sA = smem_u32(smem);
    const uint32_t sB = sA + A_BYTES;
    uint32_t* rowminS = (uint32_t*)(smem + OFF_ROWMIN);
    unsigned long long* rowbest = (unsigned long long*)(smem + OFF_ROWBEST);
    int* qcount = (int*)(smem + OFF_QCOUNT);
    int* qovf   = (int*)(smem + OFF_QOVF);
    uint32_t* myq = g_queue + (size_t)blockIdx.x * QSLAB;

    rowbest[tid] = ~0ull;
    rowminS[tid] = fmap(3.0e38f);
    if (tid == 0) { *qcount = 0; *qovf = 0; }

    // ---- Prologue: Ah (4 chunks) + B step 0 ----
    {
        const char* gA = (const char*)g_zs + (size_t)row0 * 512;
        for (int o = tid; o < 4096; o += 128) {
            int chunk = o >> 10, rem = o & 1023;
            int row = rem >> 3, seg = rem & 7;
            uint32_t dst = sA + chunk * A_CHUNK_BYTES + row * 128 +
                           (((uint32_t)(seg ^ (row & 7))) << 4);
            cp16(dst, gA + (size_t)row * 512 + chunk * 128 + seg * 16);
        }
        fill_B(sB, 0);
        CP_COMMIT();
    }
    __syncthreads();   // shared init visible

    // ===================== Single GEMM pass with gating ====================
    int s = 0;
    for (int tile = 0; tile < NTILES; ++tile) {
        float acc[4][8][4];
        #pragma unroll
        for (int mi = 0; mi < 4; ++mi)
            #pragma unroll
            for (int ni = 0; ni < 8; ++ni)
                #pragma unroll
                for (int r = 0; r < 4; ++r) acc[mi][ni][r] = 0.f;
        for (int chunk = 0; chunk < 4; ++chunk, ++s) {
            CP_WAIT0();
            __syncthreads();
            if (s + 1 < NSTEPS) { fill_B(sB, s + 1); CP_COMMIT(); }
            chunk_mma(sA + chunk * A_CHUNK_BYTES,
                      sB + (s & 1) * B_CHUNK_BYTES, lane, acc, wm, wn);
        }

        // ---- Phase 1: scores in place, register min, shared atomicMin ----
        #pragma unroll
        for (int ni = 0; ni < 8; ++ni) {
            int c0 = tile * BN + wn + ni * 8 + ((lane & 3) << 1);
            float e0 = __ldg(&g_enorm[c0]);
            float e1 = __ldg(&g_enorm[c0 + 1]);
            #pragma unroll
            for (int mi = 0; mi < 4; ++mi) {
                acc[mi][ni][0] = e0 - acc[mi][ni][0];
                acc[mi][ni][1] = e1 - acc[mi][ni][1];
                acc[mi][ni][2] = e0 - acc[mi][ni][2];
                acc[mi][ni][3] = e1 - acc[mi][ni][3];
            }
        }
        #pragma unroll
        for (int mi = 0; mi < 4; ++mi) {
            #pragma unroll
            for (int h = 0; h < 2; ++h) {
                float vmin = fminf(acc[mi][0][2*h], acc[mi][0][2*h+1]);
                #pragma unroll
                for (int ni = 1; ni < 8; ++ni)
                    vmin = fminf(vmin, fminf(acc[mi][ni][2*h], acc[mi][ni][2*h+1]));
                int rloc = wm + mi * 16 + (lane >> 2) + h * 8;
                atomicMin(&rowminS[rloc], fmap(vmin));
            }
        }
        __syncthreads();

        // ---- Phase 2: branch-free masks; one cold branch per slice ----
        #pragma unroll
        for (int mi = 0; mi < 4; ++mi) {
            #pragma unroll
            for (int h = 0; h < 2; ++h) {
                int rloc = wm + mi * 16 + (lane >> 2) + h * 8;
                float thr = funmap(rowminS[rloc]) + MARGIN;
                uint32_t mask = 0;
                #pragma unroll
                for (int ni = 0; ni < 8; ++ni) {
                    mask |= (acc[mi][ni][2*h]   < thr) ? (1u << (2*ni))     : 0u;
                    mask |= (acc[mi][ni][2*h+1] < thr) ? (1u << (2*ni + 1)) : 0u;
                }
                if (mask) {
                    int cb = tile * BN + wn + ((lane & 3) << 1);
                    do {
                        int b = __ffs(mask) - 1;
                        mask &= mask - 1;
                        int code = cb + (b >> 1) * 8 + (b & 1);
                        int qi = atomicAdd(qcount, 1);
                        if (qi < QSLAB) myq[qi] = ((uint32_t)rloc << 11) | (uint32_t)code;
                        else *qovf = 1;
                    } while (mask);
                }
            }
        }
    }

    // ======================= Exact fp32 rescore ============================
    __syncthreads();
    int qn = *qcount; if (qn > QSLAB) qn = QSLAB;
    for (int q = tid; q < qn; q += 128) {
        uint32_t ent = myq[q];
        exact_rescore(z, e, row0, (int)(ent >> 11), (int)(ent & 2047u), rowbest);
    }
    // Cold fallback: queue overflowed (never in practice) -> brute force.
    if (*qovf) {
        for (int code = 0; code < KCODES; ++code)
            exact_rescore(z, e, row0, tid, code, rowbest);
    }
    __syncthreads();

    // ---- Outputs: each thread owns one row ----
    {
        int bi = (int)(rowbest[tid] & 0xFFFFFFFFull);
        int row = row0 + tid;
        g_index[row] = bi;
        out_idx[row] = (float)bi;
        atomicAdd(&g_counts[bi], 1.0f);
    }
}

// ---------------------------------------------------------------------------
// Gather z_q + commitment-loss partials.
// ---------------------------------------------------------------------------
__global__ void gather_loss_kernel(const float* __restrict__ z,
                                   const float* __restrict__ e,
                                   float* __restrict__ out) {
    int i = blockIdx.x * blockDim.x + threadIdx.x;
    int row = i >> 6;
    int c4 = i & 63;
    int idx = g_index[row];
    float4 ev = ((const float4*)e)[(size_t)idx * 64 + c4];
    float4 zv = ((const float4*)z)[i];
    ((float4*)out)[i] = ev;
    float dx = ev.x - zv.x, dy = ev.y - zv.y;
    float dz = ev.z - zv.z, dw = ev.w - zv.w;
    float ls = dx * dx + dy * dy + dz * dz + dw * dw;

    __shared__ float red[32];
    #pragma unroll
    for (int o = 16; o; o >>= 1) ls += __shfl_xor_sync(0xffffffffu, ls, o);
    int l = threadIdx.x & 31, wq = threadIdx.x >> 5;
    if (l == 0) red[wq] = ls;
    __syncthreads();
    if (wq == 0) {
        float v = (l < ((int)blockDim.x >> 5)) ? red[l] : 0.f;
        #pragma unroll
        for (int o = 16; o; o >>= 1) v += __shfl_xor_sync(0xffffffffu, v, o);
        if (l == 0) atomicAdd(&g_loss_sum, v);
    }
}

// ---------------------------------------------------------------------------
// Finalize: loss scalar + perplexity.
// ---------------------------------------------------------------------------
__global__ void finalize_kernel(float* __restrict__ out) {
    const float invN = 1.0f / (float)NROWS;
    float s = 0.f;
    for (int k = threadIdx.x; k < KCODES; k += blockDim.x) {
        float p = g_counts[k] * invN;
        s += p * logf(p + 1e-10f);
    }
    __shared__ float red[32];
    #pragma unroll
    for (int o = 16; o; o >>= 1) s += __shfl_xor_sync(0xffffffffu, s, o);
    int l = threadIdx.x & 31, wq = threadIdx.x >> 5;
    if (l == 0) red[wq] = s;
    __syncthreads();
    if (wq == 0) {
        float v = (l < ((int)blockDim.x >> 5)) ? red[l] : 0.f;
        #pragma unroll
        for (int o = 16; o; o >>= 1) v += __shfl_xor_sync(0xffffffffu, v, o);
        if (l == 0) {
            const size_t NZ = (size_t)NROWS * DIM;
            out[NZ] = 0.25f * g_loss_sum / (float)NZ;
            out[NZ + 1 + NROWS] = expf(-v);
        }
    }
}

// ---------------------------------------------------------------------------
// Output layout (flattened tuple, float32):
//   [0, N*D) z_q_st | [N*D] loss | [N*D+1, +N) indices | [N*D+1+N] perplexity
// ---------------------------------------------------------------------------
extern "C" void kernel_launch(void* const* d_in, const int* in_sizes, int n_in,
                              void* d_out, int out_size) {
    const float* z = (const float*)d_in[0];
    const float* e = (const float*)d_in[1];
    float* out = (float*)d_out;

    cudaFuncSetAttribute(argmin_mma_kernel,
                         cudaFuncAttributeMaxDynamicSharedMemorySize, SMEM_BYTES);

    prep_z_kernel<<<(NROWS * 64) / 256, 256>>>(z);
    prep_e_kernel<<<KCODES * 32 / 256, 256>>>(e);
    argmin_mma_kernel<<<NROWS / BM, 128, SMEM_BYTES>>>(
        z, e, out + (size_t)NROWS * DIM + 1);
    gather_loss_kernel<<<(NROWS * (DIM / 4)) / 256, 256>>>(z, e, out);
    finalize_kernel<<<1, 256>>>(out);
}